// round 6
// baseline (speedup 1.0000x reference)
#include <cuda_runtime.h>
#include <math.h>

#define HH 496
#define WW 496
#define HW (HH * WW)
#define BDIM 4
#define NTOT (BDIM * HW)
#define TPB 256
#define NBLK2 (NTOT / 2 / TPB)       // 1922 blocks, 2 elements per thread
#define BLK_PER_B (HW / TPB)         // 961
#define NW (TPB / 32)

__device__ float g_num = 0.0f;
__device__ int g_cnt = 0;
__device__ unsigned int g_done = 0;

// Liang-Barsky interval update for one halfplane.
// D(t) = dc + t*(dn-dc); inside = D >= 0.
__device__ __forceinline__ void upd(float dc, float dn, float& t0, float& t1) {
    float den = dc - dn;
    float t = __fdividef(dc, den);
    if (den < 0.0f)      t0 = fmaxf(t0, t);   // D increasing -> lower bound
    else if (den > 0.0f) t1 = fminf(t1, t);   // D decreasing -> upper bound
    else if (dc < 0.0f)  t1 = -1e30f;         // parallel & outside -> empty
}

// One element's full IoU-loss term. All inputs by value -> independent DAGs.
__device__ __forceinline__ float iou_term(float pa0, float pa1, float pa2, float pa3,
                                          float pa4, float pa5, float pa6,
                                          float pb0, float pb1, float pb2, float pb3,
                                          float pb4, float pb5, float pb6,
                                          float ip) {
    const float vol_a = pa3 * pa4 * pa5;
    const float vol_b = pb3 * pb4 * pb5;
    const float zo = fmaxf(fminf(pa2 + 0.5f * pa5, pb2 + 0.5f * pb5) -
                           fmaxf(pa2 - 0.5f * pa5, pb2 - 0.5f * pb5), 0.0f);

    float sa, ca, sr, cr;
    __sincosf(pa6, &sa, &ca);
    __sincosf(pb6 - pa6, &sr, &cr);

    // Box A's frame: rotate world by -heading_a, center at A.
    const float tx = pb0 - pa0, ty = pb1 - pa1;
    const float rx = fmaf(ca, tx, sa * ty);
    const float ry = fmaf(ca, ty, -sa * tx);

    const float hx = 0.5f * pa3, hy = 0.5f * pa4;
    const float lx = 0.5f * pb3, ly = 0.5f * pb4;

    const float SX[4] = {1.f, -1.f, -1.f, 1.f};
    const float SY[4] = {1.f, 1.f, -1.f, -1.f};
    float bxx[4], byy[4];
#pragma unroll
    for (int i = 0; i < 4; i++) {
        float px_ = SX[i] * lx, py_ = SY[i] * ly;
        bxx[i] = rx + cr * px_ - sr * py_;
        byy[i] = ry + sr * px_ + cr * py_;
    }

    // Per-B-halfplane reduced coefficients:
    // D(A-corner) = {kp or km} ± eyhx; k_j doubles as B-edge shoelace cross.
    float kp[4], km[4], eyhx[4], ke[4];
#pragma unroll
    for (int j = 0; j < 4; j++) {
        int j1 = (j + 1) & 3;
        float ex = bxx[j1] - bxx[j];
        float ey = byy[j1] - byy[j];
        float k = fmaf(ey, bxx[j], -ex * byy[j]);
        ke[j] = k;
        float exhy = ex * hy;
        kp[j] = k + exhy;
        km[j] = k - exhy;
        eyhx[j] = ey * hx;
    }

    auto dA = [&](int v, int j) -> float {
        float base = (v == 0 || v == 1) ? kp[j] : km[j];
        float sgn = (v == 1 || v == 2) ? eyhx[j] : -eyhx[j];
        return base + sgn;
    };

    // Pass A: A edges clipped by B halfplanes; each cross-term = 2*hx*hy.
    float dtsum = 0.0f;
#pragma unroll
    for (int i = 0; i < 4; i++) {
        const int i1 = (i + 1) & 3;
        float t0 = 0.0f, t1 = 1.0f;
#pragma unroll
        for (int j = 0; j < 4; j++) upd(dA(i, j), dA(i1, j), t0, t1);
        dtsum += fmaxf(t1 - t0, 0.0f);
    }
    float acc = dtsum * (2.0f * hx * hy);

    // Pass B: B edges clipped by A halfplanes; cross-term = ke[j].
#pragma unroll
    for (int j = 0; j < 4; j++) {
        const int j1 = (j + 1) & 3;
        float t0 = 0.0f, t1 = 1.0f;
        upd(hy - byy[j], hy - byy[j1], t0, t1);
        upd(bxx[j] + hx, bxx[j1] + hx, t0, t1);
        upd(byy[j] + hy, byy[j1] + hy, t0, t1);
        upd(hx - bxx[j], hx - bxx[j1], t0, t1);
        acc = fmaf(fmaxf(t1 - t0, 0.0f), ke[j], acc);
    }

    const float inter_vol = 0.5f * fabsf(acc) * zo;
    const float iou = inter_vol / (vol_a + vol_b - inter_vol + 1e-7f);
    return fabsf(ip - (2.0f * iou - 1.0f));
}

__global__ void __launch_bounds__(TPB, 4) iou_k(const float* __restrict__ iou_pred,
                                                const int* __restrict__ mask,
                                                const float* __restrict__ box_pred,
                                                const float* __restrict__ box_gt,
                                                float* __restrict__ out) {
    __shared__ float s_red[NW];
    __shared__ int s_cnt[NW];

    const int tid = threadIdx.x;
    const int lane = tid & 31;
    const int w = tid >> 5;
    const int b = blockIdx.x / BLK_PER_B;           // batch of element 0 (0 or 1)
    const int n = blockIdx.x * TPB + tid;           // element 0
    const int n2 = n + NTOT / 2;                    // element 1: same hw, batch b+2
    const int hw = n - b * HW;

    // ---- all 32 loads up front: both elements, no barriers ----
    const int m0 = __ldg(mask + n);
    const int m1 = __ldg(mask + n2);
    const float ip0 = __ldg(iou_pred + n);
    const float ip1 = __ldg(iou_pred + n2);

    const float* bp0 = box_pred + (size_t)b * 7 * HW + hw;          // [B,7,H,W]
    const float* bp1 = bp0 + (size_t)2 * 7 * HW;
    float A0[7], A1[7];
#pragma unroll
    for (int c = 0; c < 7; c++) A0[c] = __ldg(bp0 + (size_t)c * HW);
#pragma unroll
    for (int c = 0; c < 7; c++) A1[c] = __ldg(bp1 + (size_t)c * HW);

    const float* bg0 = box_gt + (size_t)n * 7;                      // [B,H,W,7]
    const float* bg1 = box_gt + (size_t)n2 * 7;
    float B0[7], B1[7];
#pragma unroll
    for (int c = 0; c < 7; c++) B0[c] = __ldg(bg0 + c);
#pragma unroll
    for (int c = 0; c < 7; c++) B1[c] = __ldg(bg1 + c);

    float r0 = iou_term(A0[0], A0[1], A0[2], A0[3], A0[4], A0[5], A0[6],
                        B0[0], B0[1], B0[2], B0[3], B0[4], B0[5], B0[6], ip0);
    float r1 = iou_term(A1[0], A1[1], A1[2], A1[3], A1[4], A1[5], A1[6],
                        B1[0], B1[1], B1[2], B1[3], B1[4], B1[5], B1[6], ip1);

    float lnum = ((m0 != 0) ? r0 : 0.0f) + ((m1 != 0) ? r1 : 0.0f);
    int lcnt = __popc(__ballot_sync(0xffffffffu, m0 != 0)) +
               __popc(__ballot_sync(0xffffffffu, m1 != 0));

    // ---- block reduction ----
#pragma unroll
    for (int off = 16; off > 0; off >>= 1)
        lnum += __shfl_down_sync(0xffffffffu, lnum, off);
    if (lane == 0) { s_red[w] = lnum; s_cnt[w] = lcnt; }
    __syncthreads();
    if (w == 0) {
        lnum = (lane < NW) ? s_red[lane] : 0.0f;
        lcnt = (lane < NW) ? s_cnt[lane] : 0;
#pragma unroll
        for (int off = NW / 2; off > 0; off >>= 1) {
            lnum += __shfl_down_sync(0xffffffffu, lnum, off);
            lcnt += __shfl_down_sync(0xffffffffu, lcnt, off);
        }
        // ---- last-block finalize (threadfence reduction pattern) ----
        if (lane == 0) {
            atomicAdd(&g_num, lnum);
            atomicAdd(&g_cnt, lcnt);
            __threadfence();
            unsigned int old = atomicAdd(&g_done, 1u);
            if (old == NBLK2 - 1) {
                __threadfence();
                float num = *((volatile float*)&g_num);
                int cnt = *((volatile int*)&g_cnt);
                out[0] = num / ((float)cnt + 1e-4f);
                g_num = 0.0f;       // reset for next graph replay
                g_cnt = 0;
                g_done = 0u;
            }
        }
    }
}

extern "C" void kernel_launch(void* const* d_in, const int* in_sizes, int n_in,
                              void* d_out, int out_size) {
    const float* iou_pred = (const float*)d_in[0];
    const int* mask = (const int*)d_in[1];
    // d_in[2] = ind (unused)
    const float* box_pred = (const float*)d_in[3];
    const float* box_gt = (const float*)d_in[4];
    float* out = (float*)d_out;

    iou_k<<<NBLK2, TPB>>>(iou_pred, mask, box_pred, box_gt, out);
}

// round 7
// speedup vs baseline: 1.3658x; 1.3658x over previous
#include <cuda_runtime.h>
#include <math.h>

#define HH 496
#define WW 496
#define HW (HH * WW)
#define BDIM 4
#define NTOT (BDIM * HW)
#define TPB 256
#define BLK_PER_B (HW / TPB)         // 246016/256 = 961 exactly
#define NBLK (BDIM * BLK_PER_B)      // 3844
#define NW (TPB / 32)

__device__ float g_num = 0.0f;
__device__ int g_cnt = 0;
__device__ unsigned int g_done = 0;

// Liang-Barsky interval update for one halfplane. D(t) = dc - t*den, den = dc-dn.
// Fast-math div handles den==0 for free: dc<0 -> t=-inf -> t1 empty (correct);
// dc>0 -> +inf -> no-op; dc==0 -> NaN, fmin/fmax drop NaN -> no-op (boundary).
__device__ __forceinline__ void upd(float dc, float dn, float& t0, float& t1) {
    float den = dc - dn;
    float t = __fdividef(dc, den);
    if (den < 0.0f) t0 = fmaxf(t0, t);   // entering
    else            t1 = fminf(t1, t);   // leaving (or parallel handled via inf/NaN)
}

__global__ void __launch_bounds__(TPB, 5) iou_k(const float* __restrict__ iou_pred,
                                                const int* __restrict__ mask,
                                                const float* __restrict__ box_pred,
                                                const float* __restrict__ box_gt,
                                                float* __restrict__ out) {
    __shared__ float s_red[NW];
    __shared__ int s_cnt[NW];

    const int tid = threadIdx.x;
    const int lane = tid & 31;
    const int w = tid >> 5;
    const int b = blockIdx.x / BLK_PER_B;
    const int n = blockIdx.x * TPB + tid;
    const int hw = n - b * HW;

    // ---- issue all loads up front: no barriers, maximal MLP ----
    const int m = __ldg(mask + n);
    const float ip = __ldg(iou_pred + n);

    const float* bp = box_pred + (size_t)b * 7 * HW + hw;   // [B,7,H,W] (coalesced)
    const float pa0 = __ldg(bp);
    const float pa1 = __ldg(bp + HW);
    const float pa2 = __ldg(bp + 2 * HW);
    const float pa3 = __ldg(bp + 3 * HW);
    const float pa4 = __ldg(bp + 4 * HW);
    const float pa5 = __ldg(bp + 5 * HW);
    const float pa6 = __ldg(bp + 6 * HW);

    const float* bg = box_gt + (size_t)n * 7;               // [B,H,W,7]
    const float pb0 = __ldg(bg);
    const float pb1 = __ldg(bg + 1);
    const float pb2 = __ldg(bg + 2);
    const float pb3 = __ldg(bg + 3);
    const float pb4 = __ldg(bg + 4);
    const float pb5 = __ldg(bg + 5);
    const float pb6 = __ldg(bg + 6);

    // Fold z/volume terms immediately so pa2/pa5/pb2/pb5 die early.
    const float vol_a = pa3 * pa4 * pa5;
    const float vol_b = pb3 * pb4 * pb5;
    const float zo = fmaxf(fminf(pa2 + 0.5f * pa5, pb2 + 0.5f * pb5) -
                           fmaxf(pa2 - 0.5f * pa5, pb2 - 0.5f * pb5), 0.0f);

    // Start MUFU chains early.
    float sa, ca, sr, cr;
    __sincosf(pa6, &sa, &ca);
    __sincosf(pb6 - pa6, &sr, &cr);

    // Box A's frame: rotate world by -heading_a, center at A.
    const float tx = pb0 - pa0, ty = pb1 - pa1;
    const float rx = fmaf(ca, tx, sa * ty);
    const float ry = fmaf(ca, ty, -sa * tx);

    const float hx = 0.5f * pa3, hy = 0.5f * pa4;
    const float lx = 0.5f * pb3, ly = 0.5f * pb4;

    // B corners (CCW); A corners are (+-hx, +-hy) implicit.
    const float SX[4] = {1.f, -1.f, -1.f, 1.f};
    const float SY[4] = {1.f, 1.f, -1.f, -1.f};
    float bxx[4], byy[4];
#pragma unroll
    for (int i = 0; i < 4; i++) {
        float px_ = SX[i] * lx, py_ = SY[i] * ly;
        bxx[i] = rx + cr * px_ - sr * py_;
        byy[i] = ry + sr * px_ + cr * py_;
    }

    // Per-B-halfplane reduced coefficients (no DA/DB arrays):
    // D(A-corner) = {kp or km} ± eyhx; k_j doubles as B-edge shoelace cross.
    float kp[4], km[4], eyhx[4], ke[4];
#pragma unroll
    for (int j = 0; j < 4; j++) {
        int j1 = (j + 1) & 3;
        float ex = bxx[j1] - bxx[j];
        float ey = byy[j1] - byy[j];
        float k = fmaf(ey, bxx[j], -ex * byy[j]);
        ke[j] = k;
        float exhy = ex * hy;
        kp[j] = k + exhy;
        km[j] = k - exhy;
        eyhx[j] = ey * hx;
    }

    // A-corner j-th halfplane distance, vertex ((+,+),(-,+),(-,-),(+,-)).
    auto dA = [&](int v, int j) -> float {
        float base = (v == 0 || v == 1) ? kp[j] : km[j];
        float sgn = (v == 1 || v == 2) ? eyhx[j] : -eyhx[j];
        return base + sgn;
    };

    // Pass A: A edges clipped by B halfplanes; each cross-term = 2*hx*hy.
    float dtsum = 0.0f;
#pragma unroll
    for (int i = 0; i < 4; i++) {
        const int i1 = (i + 1) & 3;
        float t0 = 0.0f, t1 = 1.0f;
#pragma unroll
        for (int j = 0; j < 4; j++) upd(dA(i, j), dA(i1, j), t0, t1);
        dtsum += fmaxf(t1 - t0, 0.0f);
    }
    float acc = dtsum * (2.0f * hx * hy);

    // Pass B: B edges clipped by A halfplanes (distances on the fly);
    // cross-term = ke[j].
#pragma unroll
    for (int j = 0; j < 4; j++) {
        const int j1 = (j + 1) & 3;
        float t0 = 0.0f, t1 = 1.0f;
        upd(hy - byy[j], hy - byy[j1], t0, t1);
        upd(bxx[j] + hx, bxx[j1] + hx, t0, t1);
        upd(byy[j] + hy, byy[j1] + hy, t0, t1);
        upd(hx - bxx[j], hx - bxx[j1], t0, t1);
        acc = fmaf(fmaxf(t1 - t0, 0.0f), ke[j], acc);
    }

    const float inter_vol = 0.5f * fabsf(acc) * zo;
    const float iou = __fdividef(inter_vol, vol_a + vol_b - inter_vol + 1e-7f);

    float lnum = (m != 0) ? fabsf(ip - (2.0f * iou - 1.0f)) : 0.0f;
    int lcnt = __popc(__ballot_sync(0xffffffffu, m != 0));

    // ---- block reduction ----
#pragma unroll
    for (int off = 16; off > 0; off >>= 1)
        lnum += __shfl_down_sync(0xffffffffu, lnum, off);
    if (lane == 0) { s_red[w] = lnum; s_cnt[w] = lcnt; }
    __syncthreads();
    if (w == 0) {
        lnum = (lane < NW) ? s_red[lane] : 0.0f;
        lcnt = (lane < NW) ? s_cnt[lane] : 0;
#pragma unroll
        for (int off = NW / 2; off > 0; off >>= 1) {
            lnum += __shfl_down_sync(0xffffffffu, lnum, off);
            lcnt += __shfl_down_sync(0xffffffffu, lcnt, off);
        }
        // ---- last-block finalize (threadfence reduction pattern) ----
        if (lane == 0) {
            atomicAdd(&g_num, lnum);
            atomicAdd(&g_cnt, lcnt);
            __threadfence();
            unsigned int old = atomicAdd(&g_done, 1u);
            if (old == NBLK - 1) {
                __threadfence();
                float num = *((volatile float*)&g_num);
                int cnt = *((volatile int*)&g_cnt);
                out[0] = num / ((float)cnt + 1e-4f);
                g_num = 0.0f;       // reset for next graph replay
                g_cnt = 0;
                g_done = 0u;
            }
        }
    }
}

extern "C" void kernel_launch(void* const* d_in, const int* in_sizes, int n_in,
                              void* d_out, int out_size) {
    const float* iou_pred = (const float*)d_in[0];
    const int* mask = (const int*)d_in[1];
    // d_in[2] = ind (unused)
    const float* box_pred = (const float*)d_in[3];
    const float* box_gt = (const float*)d_in[4];
    float* out = (float*)d_out;

    iou_k<<<NBLK, TPB>>>(iou_pred, mask, box_pred, box_gt, out);
}

// round 8
// speedup vs baseline: 1.4992x; 1.0977x over previous
#include <cuda_runtime.h>
#include <math.h>

#define HH 496
#define WW 496
#define HW (HH * WW)
#define BDIM 4
#define NTOT (BDIM * HW)
#define TPB 256
#define BLK_PER_B (HW / TPB)         // 246016/256 = 961 exactly
#define NBLK (BDIM * BLK_PER_B)      // 3844
#define NW (TPB / 32)

__device__ float g_num = 0.0f;
__device__ int g_cnt = 0;
__device__ unsigned int g_done = 0;

__global__ void __launch_bounds__(TPB, 5) iou_k(const float* __restrict__ iou_pred,
                                                const int* __restrict__ mask,
                                                const float* __restrict__ box_pred,
                                                const float* __restrict__ box_gt,
                                                float* __restrict__ out) {
    __shared__ float s_red[NW];
    __shared__ int s_cnt[NW];

    const int tid = threadIdx.x;
    const int lane = tid & 31;
    const int w = tid >> 5;
    const int b = blockIdx.x / BLK_PER_B;
    const int n = blockIdx.x * TPB + tid;
    const int hw = n - b * HW;

    // ---- issue all loads up front: no barriers, maximal MLP ----
    const int m = __ldg(mask + n);
    const float ip = __ldg(iou_pred + n);

    const float* bp = box_pred + (size_t)b * 7 * HW + hw;   // [B,7,H,W] (coalesced)
    const float pa0 = __ldg(bp);
    const float pa1 = __ldg(bp + HW);
    const float pa2 = __ldg(bp + 2 * HW);
    const float pa3 = __ldg(bp + 3 * HW);
    const float pa4 = __ldg(bp + 4 * HW);
    const float pa5 = __ldg(bp + 5 * HW);
    const float pa6 = __ldg(bp + 6 * HW);

    const float* bg = box_gt + (size_t)n * 7;               // [B,H,W,7]
    const float pb0 = __ldg(bg);
    const float pb1 = __ldg(bg + 1);
    const float pb2 = __ldg(bg + 2);
    const float pb3 = __ldg(bg + 3);
    const float pb4 = __ldg(bg + 4);
    const float pb5 = __ldg(bg + 5);
    const float pb6 = __ldg(bg + 6);

    // Fold z/volume terms immediately so pa2/pa5/pb2/pb5 die early.
    const float vol_a = pa3 * pa4 * pa5;
    const float vol_b = pb3 * pb4 * pb5;
    const float zo = fmaxf(fminf(pa2 + 0.5f * pa5, pb2 + 0.5f * pb5) -
                           fmaxf(pa2 - 0.5f * pa5, pb2 - 0.5f * pb5), 0.0f);

    // Start MUFU chains early.
    float sa, ca, sr, cr;
    __sincosf(pa6, &sa, &ca);
    __sincosf(pb6 - pa6, &sr, &cr);

    // Box A's frame: rotate world by -heading_a, center at A.
    const float tx = pb0 - pa0, ty = pb1 - pa1;
    const float rx = fmaf(ca, tx, sa * ty);
    const float ry = fmaf(ca, ty, -sa * tx);

    const float hx = 0.5f * pa3, hy = 0.5f * pa4;
    const float lx = 0.5f * pb3, ly = 0.5f * pb4;
    const float rhx2 = __fdividef(1.0f, hx + hx);
    const float rhy2 = __fdividef(1.0f, hy + hy);

    // B corners (CCW); A corners are (+hx,+hy),(-hx,+hy),(-hx,-hy),(+hx,-hy).
    const float SX[4] = {1.f, -1.f, -1.f, 1.f};
    const float SY[4] = {1.f, 1.f, -1.f, -1.f};
    float bxx[4], byy[4];
#pragma unroll
    for (int i = 0; i < 4; i++) {
        float px_ = SX[i] * lx, py_ = SY[i] * ly;
        bxx[i] = rx + cr * px_ - sr * py_;
        byy[i] = ry + sr * px_ + cr * py_;
    }

    // Pass-A per-edge parametric intervals (A edges: top,left,bottom,right).
    float t0a0 = 0.f, t1a0 = 1.f, t0a1 = 0.f, t1a1 = 1.f;
    float t0a2 = 0.f, t1a2 = 1.f, t0a3 = 0.f, t1a3 = 1.f;
    float acc = 0.0f;

#pragma unroll
    for (int j = 0; j < 4; j++) {
        const int j1 = (j + 1) & 3;
        const float bx = bxx[j], by = byy[j];
        const float ex = bxx[j1] - bx;
        const float ey = byy[j1] - by;
        const float k = fmaf(ey, bx, -ex * by);     // also B-edge shoelace cross
        const float rex = __fdividef(1.0f, ex);
        const float rey = __fdividef(1.0f, ey);
        const bool eyp = ey > 0.0f, eyn = ey < 0.0f;
        const bool exp_ = ex > 0.0f, exn = ex < 0.0f;

        // ---- Pass A: B-halfplane j vs the 4 axis-aligned A edges ----
        const float exhy = ex * hy, eyhx = ey * hx;
        const float kp = k + exhy, km = k - exhy;
        const float u = rhx2 * rey;    // 1/(2 hx ey)
        const float v = rhy2 * rex;    // 1/(2 hy ex)
        {   // top edge: dc = kp - eyhx, den = -2 hx ey
            float t = -(kp - eyhx) * u;
            if (eyp) t0a0 = fmaxf(t0a0, t); else t1a0 = fminf(t1a0, t);
        }
        {   // left edge: dc = kp + eyhx, den = +2 ex hy
            float t = (kp + eyhx) * v;
            if (exn) t0a1 = fmaxf(t0a1, t); else t1a1 = fminf(t1a1, t);
        }
        {   // bottom edge: dc = km + eyhx, den = +2 hx ey
            float t = (km + eyhx) * u;
            if (eyn) t0a2 = fmaxf(t0a2, t); else t1a2 = fminf(t1a2, t);
        }
        {   // right edge: dc = km - eyhx, den = -2 ex hy
            float t = -(km - eyhx) * v;
            if (exp_) t0a3 = fmaxf(t0a3, t); else t1a3 = fminf(t1a3, t);
        }

        // ---- Pass B: B edge j vs the 4 A halfplanes (slab test) ----
        float t0 = 0.0f, t1 = 1.0f;
        {   // y <= hy: den = ey
            float t = (hy - by) * rey;
            if (eyn) t0 = fmaxf(t0, t); else t1 = fminf(t1, t);
        }
        {   // x >= -hx: den = -ex
            float t = -(bx + hx) * rex;
            if (exp_) t0 = fmaxf(t0, t); else t1 = fminf(t1, t);
        }
        {   // y >= -hy: den = -ey
            float t = -(by + hy) * rey;
            if (eyp) t0 = fmaxf(t0, t); else t1 = fminf(t1, t);
        }
        {   // x <= hx: den = ex
            float t = (hx - bx) * rex;
            if (exn) t0 = fmaxf(t0, t); else t1 = fminf(t1, t);
        }
        acc = fmaf(fmaxf(t1 - t0, 0.0f), k, acc);
    }

    // A-edge contributions: each cross-term = 2*hx*hy.
    const float dtsum = fmaxf(t1a0 - t0a0, 0.f) + fmaxf(t1a1 - t0a1, 0.f) +
                        fmaxf(t1a2 - t0a2, 0.f) + fmaxf(t1a3 - t0a3, 0.f);
    acc = fmaf(dtsum, 2.0f * hx * hy, acc);

    const float inter_vol = 0.5f * fabsf(acc) * zo;
    const float iou = __fdividef(inter_vol, vol_a + vol_b - inter_vol + 1e-7f);

    float lnum = (m != 0) ? fabsf(ip - (2.0f * iou - 1.0f)) : 0.0f;
    int lcnt = __popc(__ballot_sync(0xffffffffu, m != 0));

    // ---- block reduction ----
#pragma unroll
    for (int off = 16; off > 0; off >>= 1)
        lnum += __shfl_down_sync(0xffffffffu, lnum, off);
    if (lane == 0) { s_red[w] = lnum; s_cnt[w] = lcnt; }
    __syncthreads();
    if (w == 0) {
        lnum = (lane < NW) ? s_red[lane] : 0.0f;
        lcnt = (lane < NW) ? s_cnt[lane] : 0;
#pragma unroll
        for (int off = NW / 2; off > 0; off >>= 1) {
            lnum += __shfl_down_sync(0xffffffffu, lnum, off);
            lcnt += __shfl_down_sync(0xffffffffu, lcnt, off);
        }
        // ---- last-block finalize (threadfence reduction pattern) ----
        if (lane == 0) {
            atomicAdd(&g_num, lnum);
            atomicAdd(&g_cnt, lcnt);
            __threadfence();
            unsigned int old = atomicAdd(&g_done, 1u);
            if (old == NBLK - 1) {
                __threadfence();
                float num = *((volatile float*)&g_num);
                int cnt = *((volatile int*)&g_cnt);
                out[0] = num / ((float)cnt + 1e-4f);
                g_num = 0.0f;       // reset for next graph replay
                g_cnt = 0;
                g_done = 0u;
            }
        }
    }
}

extern "C" void kernel_launch(void* const* d_in, const int* in_sizes, int n_in,
                              void* d_out, int out_size) {
    const float* iou_pred = (const float*)d_in[0];
    const int* mask = (const int*)d_in[1];
    // d_in[2] = ind (unused)
    const float* box_pred = (const float*)d_in[3];
    const float* box_gt = (const float*)d_in[4];
    float* out = (float*)d_out;

    iou_k<<<NBLK, TPB>>>(iou_pred, mask, box_pred, box_gt, out);
}

// round 9
// speedup vs baseline: 1.6367x; 1.0917x over previous
#include <cuda_runtime.h>
#include <math.h>

#define HH 496
#define WW 496
#define HW (HH * WW)
#define BDIM 4
#define NTOT (BDIM * HW)
#define TPB 256
#define BLK_PER_B (HW / TPB)         // 246016/256 = 961 exactly
#define NBLK (BDIM * BLK_PER_B)      // 3844
#define NW (TPB / 32)

__device__ float g_num = 0.0f;
__device__ int g_cnt = 0;
__device__ unsigned int g_done = 0;

__global__ void __launch_bounds__(TPB, 5) iou_k(const float* __restrict__ iou_pred,
                                                const int* __restrict__ mask,
                                                const float* __restrict__ box_pred,
                                                const float* __restrict__ box_gt,
                                                float* __restrict__ out) {
    __shared__ float s_red[NW];
    __shared__ int s_cnt[NW];

    const int tid = threadIdx.x;
    const int lane = tid & 31;
    const int w = tid >> 5;
    const int b = blockIdx.x / BLK_PER_B;
    const int n = blockIdx.x * TPB + tid;
    const int hw = n - b * HW;

    // ---- issue all loads up front: no barriers, maximal MLP ----
    const int m = __ldg(mask + n);
    const float ip = __ldg(iou_pred + n);

    const float* bp = box_pred + (size_t)b * 7 * HW + hw;   // [B,7,H,W] (coalesced)
    const float pa0 = __ldg(bp);
    const float pa1 = __ldg(bp + HW);
    const float pa2 = __ldg(bp + 2 * HW);
    const float pa3 = __ldg(bp + 3 * HW);
    const float pa4 = __ldg(bp + 4 * HW);
    const float pa5 = __ldg(bp + 5 * HW);
    const float pa6 = __ldg(bp + 6 * HW);

    const float* bg = box_gt + (size_t)n * 7;               // [B,H,W,7]
    const float pb0 = __ldg(bg);
    const float pb1 = __ldg(bg + 1);
    const float pb2 = __ldg(bg + 2);
    const float pb3 = __ldg(bg + 3);
    const float pb4 = __ldg(bg + 4);
    const float pb5 = __ldg(bg + 5);
    const float pb6 = __ldg(bg + 6);

    // Fold z/volume terms immediately so pa2/pa5/pb2/pb5 die early.
    const float vol_a = pa3 * pa4 * pa5;
    const float vol_b = pb3 * pb4 * pb5;
    const float zo = fmaxf(fminf(pa2 + 0.5f * pa5, pb2 + 0.5f * pb5) -
                           fmaxf(pa2 - 0.5f * pa5, pb2 - 0.5f * pb5), 0.0f);

    // MUFU chains early.
    float sa, ca, sr, cr;
    __sincosf(pa6, &sa, &ca);
    __sincosf(pb6 - pa6, &sr, &cr);

    // Box A's frame: rotate world by -heading_a, center at A. A is the AABB
    // [-hx,hx] x [-hy,hy]; B is a rotated rect centered (rx,ry).
    const float tx = pb0 - pa0, ty = pb1 - pa1;
    const float rx = fmaf(ca, tx, sa * ty);
    const float ry = fmaf(ca, ty, -sa * tx);

    const float hx = 0.5f * pa3, hy = 0.5f * pa4;
    const float lx = 0.5f * pb3, ly = 0.5f * pb4;

    // B corners CCW: c2 = 2T - c0, c3 = 2T - c1.
    const float crlx = cr * lx, srlx = sr * lx;
    const float crly = cr * ly, srly = sr * ly;
    const float c0x = rx + crlx - srly, c0y = ry + srlx + crly;
    const float c1x = rx - crlx - srly, c1y = ry - srlx + crly;
    const float c2x = 2.0f * rx - c0x,  c2y = 2.0f * ry - c0y;
    const float c3x = 2.0f * rx - c1x,  c3y = 2.0f * ry - c1y;

    // Edge vectors: e0 = c1-c0, e1 = c2-c1; e2 = -e0, e3 = -e1.
    const float ex0 = -2.0f * crlx, ey0 = -2.0f * srlx;
    const float ex1 =  2.0f * srly, ey1 = -2.0f * crly;

    // 6 reciprocals total (shared across all 32 interval updates).
    const float rex0 = __fdividef(1.0f, ex0);
    const float rey0 = __fdividef(1.0f, ey0);
    const float rex1 = __fdividef(1.0f, ex1);
    const float rey1 = __fdividef(1.0f, ey1);
    const float rhx2 = __fdividef(1.0f, hx + hx);
    const float rhy2 = __fdividef(1.0f, hy + hy);

    // Shoelace cross per B edge: k_j = ey_j*c_jx - ex_j*c_jy.
    const float k0 = fmaf(ey0, c0x, -ex0 * c0y);
    const float k1 = fmaf(ey1, c1x, -ex1 * c1y);
    const float k2 = fmaf(-ey0, c2x, ex0 * c2y);
    const float k3 = fmaf(-ey1, c3x, ex1 * c3y);

    float acc = 0.0f;

    // ---- Pass B: B edges vs A AABB (branchless slab test) ----
    {
        auto slabB = [&](float cx, float cy, float rex, float rey, float k) {
            float tx1 = (-hx - cx) * rex, tx2 = (hx - cx) * rex;
            float ty1 = (-hy - cy) * rey, ty2 = (hy - cy) * rey;
            float t0 = fmaxf(fmaxf(fminf(tx1, tx2), fminf(ty1, ty2)), 0.0f);
            float t1 = fminf(fminf(fmaxf(tx1, tx2), fmaxf(ty1, ty2)), 1.0f);
            acc = fmaf(fmaxf(t1 - t0, 0.0f), k, acc);
        };
        slabB(c0x, c0y,  rex0,  rey0, k0);
        slabB(c1x, c1y,  rex1,  rey1, k1);
        slabB(c2x, c2y, -rex0, -rey0, k2);
        slabB(c3x, c3y, -rex1, -rey1, k3);
    }

    // ---- Pass A: A edges vs B rect (strip pairs {0,2},{1,3}, branchless) ----
    {
        // D_j at A corners: D_j(+-hx, +-hy) = k_j + ex_j*(+-hy) - ey_j*(+-hx).
        const float exhy0 = ex0 * hy, eyhx0 = ey0 * hx;
        const float exhy1 = ex1 * hy, eyhx1 = ey1 * hx;
        const float kp0 = k0 + exhy0, km0 = k0 - exhy0;
        const float kp1 = k1 + exhy1, km1 = k1 - exhy1;
        const float kp2 = k2 - exhy0, km2 = k2 + exhy0;   // ex2 = -ex0
        const float kp3 = k3 - exhy1, km3 = k3 + exhy1;

        const float w0 = rhx2 * rey0, w1 = rhx2 * rey1;   // 1/(2 hx ey_j)
        const float v0 = rhy2 * rex0, v1 = rhy2 * rex1;   // 1/(2 hy ex_j)

        auto edgeA = [&](float ta0, float tb0, float ta1, float tb1) -> float {
            float t0 = fmaxf(fmaxf(fminf(ta0, tb0), fminf(ta1, tb1)), 0.0f);
            float t1 = fminf(fminf(fmaxf(ta0, tb0), fmaxf(ta1, tb1)), 1.0f);
            return fmaxf(t1 - t0, 0.0f);
        };

        // Top:    V=(+hx,+hy), d=(-2hx,0):  1/s_j = +w_j
        const float Dpp0 = kp0 - eyhx0, Dpp1 = kp1 - eyhx1;
        const float Dpp2 = kp2 + eyhx0, Dpp3 = kp3 + eyhx1;  // ey2 = -ey0
        float dts = edgeA(-Dpp0 * w0, Dpp2 * w0, -Dpp1 * w1, Dpp3 * w1);

        // Left:   V=(-hx,+hy), d=(0,-2hy):  1/s_j = -v_j
        const float Dmp0 = kp0 + eyhx0, Dmp1 = kp1 + eyhx1;
        const float Dmp2 = kp2 - eyhx0, Dmp3 = kp3 - eyhx1;
        dts += edgeA(Dmp0 * v0, -Dmp2 * v0, Dmp1 * v1, -Dmp3 * v1);

        // Bottom: V=(-hx,-hy), d=(+2hx,0):  1/s_j = -w_j
        const float Dmm0 = km0 + eyhx0, Dmm1 = km1 + eyhx1;
        const float Dmm2 = km2 - eyhx0, Dmm3 = km3 - eyhx1;
        dts += edgeA(Dmm0 * w0, -Dmm2 * w0, Dmm1 * w1, -Dmm3 * w1);

        // Right:  V=(+hx,-hy), d=(0,+2hy):  1/s_j = +v_j
        const float Dpm0 = km0 - eyhx0, Dpm1 = km1 - eyhx1;
        const float Dpm2 = km2 + eyhx0, Dpm3 = km3 + eyhx1;
        dts += edgeA(-Dpm0 * v0, Dpm2 * v0, -Dpm1 * v1, Dpm3 * v1);

        // Every A-edge cross-term = cross(V, d) = 2*hx*hy.
        acc = fmaf(dts, 2.0f * hx * hy, acc);
    }

    const float inter_vol = 0.5f * fabsf(acc) * zo;
    const float iou = __fdividef(inter_vol, vol_a + vol_b - inter_vol + 1e-7f);

    float lnum = (m != 0) ? fabsf(ip - (2.0f * iou - 1.0f)) : 0.0f;
    int lcnt = __popc(__ballot_sync(0xffffffffu, m != 0));

    // ---- block reduction ----
#pragma unroll
    for (int off = 16; off > 0; off >>= 1)
        lnum += __shfl_down_sync(0xffffffffu, lnum, off);
    if (lane == 0) { s_red[w] = lnum; s_cnt[w] = lcnt; }
    __syncthreads();
    if (w == 0) {
        lnum = (lane < NW) ? s_red[lane] : 0.0f;
        lcnt = (lane < NW) ? s_cnt[lane] : 0;
#pragma unroll
        for (int off = NW / 2; off > 0; off >>= 1) {
            lnum += __shfl_down_sync(0xffffffffu, lnum, off);
            lcnt += __shfl_down_sync(0xffffffffu, lcnt, off);
        }
        // ---- last-block finalize (threadfence reduction pattern) ----
        if (lane == 0) {
            atomicAdd(&g_num, lnum);
            atomicAdd(&g_cnt, lcnt);
            __threadfence();
            unsigned int old = atomicAdd(&g_done, 1u);
            if (old == NBLK - 1) {
                __threadfence();
                float num = *((volatile float*)&g_num);
                int cnt = *((volatile int*)&g_cnt);
                out[0] = num / ((float)cnt + 1e-4f);
                g_num = 0.0f;       // reset for next graph replay
                g_cnt = 0;
                g_done = 0u;
            }
        }
    }
}

extern "C" void kernel_launch(void* const* d_in, const int* in_sizes, int n_in,
                              void* d_out, int out_size) {
    const float* iou_pred = (const float*)d_in[0];
    const int* mask = (const int*)d_in[1];
    // d_in[2] = ind (unused)
    const float* box_pred = (const float*)d_in[3];
    const float* box_gt = (const float*)d_in[4];
    float* out = (float*)d_out;

    iou_k<<<NBLK, TPB>>>(iou_pred, mask, box_pred, box_gt, out);
}

// round 10
// speedup vs baseline: 1.8287x; 1.1173x over previous
#include <cuda_runtime.h>
#include <math.h>

#define HH 496
#define WW 496
#define HW (HH * WW)
#define BDIM 4
#define NTOT (BDIM * HW)
#define TPB 256
#define BLK_PER_B (HW / TPB)         // 246016/256 = 961 exactly
#define NBLK (BDIM * BLK_PER_B)      // 3844
#define NW (TPB / 32)

__device__ float g_num = 0.0f;
__device__ int g_cnt = 0;
__device__ unsigned int g_done = 0;

__global__ void __launch_bounds__(TPB, 6) iou_k(const float* __restrict__ iou_pred,
                                                const int* __restrict__ mask,
                                                const float* __restrict__ box_pred,
                                                const float* __restrict__ box_gt,
                                                float* __restrict__ out) {
    __shared__ float s_red[NW];
    __shared__ int s_cnt[NW];

    const int tid = threadIdx.x;
    const int lane = tid & 31;
    const int w = tid >> 5;
    const int b = blockIdx.x / BLK_PER_B;
    const int n = blockIdx.x * TPB + tid;
    const int hw = n - b * HW;

    // ---- issue all loads up front: no barriers, maximal MLP ----
    const int m = __ldg(mask + n);
    const float ip = __ldg(iou_pred + n);

    const float* bp = box_pred + (size_t)b * 7 * HW + hw;   // [B,7,H,W] (coalesced)
    const float pa0 = __ldg(bp);
    const float pa1 = __ldg(bp + HW);
    const float pa2 = __ldg(bp + 2 * HW);
    const float pa3 = __ldg(bp + 3 * HW);
    const float pa4 = __ldg(bp + 4 * HW);
    const float pa5 = __ldg(bp + 5 * HW);
    const float pa6 = __ldg(bp + 6 * HW);

    const float* bg = box_gt + (size_t)n * 7;               // [B,H,W,7]
    const float pb0 = __ldg(bg);
    const float pb1 = __ldg(bg + 1);
    const float pb2 = __ldg(bg + 2);
    const float pb3 = __ldg(bg + 3);
    const float pb4 = __ldg(bg + 4);
    const float pb5 = __ldg(bg + 5);
    const float pb6 = __ldg(bg + 6);

    // Fold z/volume terms immediately; keep only two live scalars (s, zo).
    const float s = fmaf(pa3 * pa4, pa5, fmaf(pb3 * pb4, pb5, 1e-7f)); // vol_a+vol_b+eps
    const float zo = fmaxf(fminf(pa2 + 0.5f * pa5, pb2 + 0.5f * pb5) -
                           fmaxf(pa2 - 0.5f * pa5, pb2 - 0.5f * pb5), 0.0f);

    // MUFU chains early.
    float sa, ca, sr, cr;
    __sincosf(pa6, &sa, &ca);
    __sincosf(pb6 - pa6, &sr, &cr);

    // Box A's frame: rotate world by -heading_a, center at A. A is the AABB
    // [-hx,hx] x [-hy,hy]; B is a rotated rect centered (rx,ry).
    const float tx = pb0 - pa0, ty = pb1 - pa1;
    const float rx = fmaf(ca, tx, sa * ty);
    const float ry = fmaf(ca, ty, -sa * tx);

    const float hx = 0.5f * pa3, hy = 0.5f * pa4;
    const float lx = 0.5f * pb3, ly = 0.5f * pb4;

    // B corners CCW (c2 = 2T - c0, c3 = 2T - c1; c2/c3 not materialized).
    const float crlx = cr * lx, srlx = sr * lx;
    const float crly = cr * ly, srly = sr * ly;
    const float c0x = rx + crlx - srly, c0y = ry + srlx + crly;
    const float c1x = rx - crlx - srly, c1y = ry - srlx + crly;

    // Edge vectors: e0 = c1-c0, e1 = c2-c1; e2 = -e0, e3 = -e1.
    const float ex0 = -2.0f * crlx, ey0 = -2.0f * srlx;
    const float ex1 =  2.0f * srly, ey1 = -2.0f * crly;

    // 6 reciprocals total (shared across all 32 interval updates).
    const float rex0 = __fdividef(1.0f, ex0);
    const float rey0 = __fdividef(1.0f, ey0);
    const float rex1 = __fdividef(1.0f, ex1);
    const float rey1 = __fdividef(1.0f, ey1);
    const float rhx2 = __fdividef(1.0f, hx + hx);
    const float rhy2 = __fdividef(1.0f, hy + hy);

    // Shoelace cross per B edge: k_j = ey_j*c_jx - ex_j*c_jy.
    // k2 = k0 - 2*(ey0*rx - ex0*ry), k3 = k1 - 2*(ey1*rx - ex1*ry).
    const float k0 = fmaf(ey0, c0x, -ex0 * c0y);
    const float k1 = fmaf(ey1, c1x, -ex1 * c1y);
    const float kc0 = fmaf(ey0, rx, -ex0 * ry);
    const float kc1 = fmaf(ey1, rx, -ex1 * ry);
    const float k2 = k0 - 2.0f * kc0;
    const float k3 = k1 - 2.0f * kc1;

    float acc = 0.0f;

    // ---- Pass B: B edges vs A AABB (branchless slab test) ----
    {
        auto slabB = [&](float cx, float cy, float rex, float rey, float k) {
            float tx1 = (-hx - cx) * rex, tx2 = (hx - cx) * rex;
            float ty1 = (-hy - cy) * rey, ty2 = (hy - cy) * rey;
            float t0 = fmaxf(fmaxf(fminf(tx1, tx2), fminf(ty1, ty2)), 0.0f);
            float t1 = fminf(fminf(fmaxf(tx1, tx2), fmaxf(ty1, ty2)), 1.0f);
            acc = fmaf(fmaxf(t1 - t0, 0.0f), k, acc);
        };
        slabB(c0x, c0y,  rex0,  rey0, k0);
        slabB(c1x, c1y,  rex1,  rey1, k1);
        slabB(2.0f * rx - c0x, 2.0f * ry - c0y, -rex0, -rey0, k2);
        slabB(2.0f * rx - c1x, 2.0f * ry - c1y, -rex1, -rey1, k3);
    }

    // ---- Pass A: A edges vs B rect (strip pairs {0,2},{1,3}, branchless) ----
    {
        // D_j at A corners: D_j(+-hx, +-hy) = k_j + ex_j*(+-hy) - ey_j*(+-hx).
        const float exhy0 = ex0 * hy, eyhx0 = ey0 * hx;
        const float exhy1 = ex1 * hy, eyhx1 = ey1 * hx;
        const float kp0 = k0 + exhy0, km0 = k0 - exhy0;
        const float kp1 = k1 + exhy1, km1 = k1 - exhy1;
        const float kp2 = k2 - exhy0, km2 = k2 + exhy0;   // ex2 = -ex0
        const float kp3 = k3 - exhy1, km3 = k3 + exhy1;

        const float w0 = rhx2 * rey0, w1 = rhx2 * rey1;   // 1/(2 hx ey_j)
        const float v0 = rhy2 * rex0, v1 = rhy2 * rex1;   // 1/(2 hy ex_j)

        auto edgeA = [&](float ta0, float tb0, float ta1, float tb1) -> float {
            float t0 = fmaxf(fmaxf(fminf(ta0, tb0), fminf(ta1, tb1)), 0.0f);
            float t1 = fminf(fminf(fmaxf(ta0, tb0), fmaxf(ta1, tb1)), 1.0f);
            return fmaxf(t1 - t0, 0.0f);
        };

        // Top:    V=(+hx,+hy), d=(-2hx,0):  1/s_j = +w_j
        float dts = edgeA(-(kp0 - eyhx0) * w0, (kp2 + eyhx0) * w0,
                          -(kp1 - eyhx1) * w1, (kp3 + eyhx1) * w1);
        // Left:   V=(-hx,+hy), d=(0,-2hy):  1/s_j = -v_j
        dts += edgeA((kp0 + eyhx0) * v0, -(kp2 - eyhx0) * v0,
                     (kp1 + eyhx1) * v1, -(kp3 - eyhx1) * v1);
        // Bottom: V=(-hx,-hy), d=(+2hx,0):  1/s_j = -w_j
        dts += edgeA((km0 + eyhx0) * w0, -(km2 - eyhx0) * w0,
                     (km1 + eyhx1) * w1, -(km3 - eyhx1) * w1);
        // Right:  V=(+hx,-hy), d=(0,+2hy):  1/s_j = +v_j
        dts += edgeA(-(km0 - eyhx0) * v0, (km2 + eyhx0) * v0,
                     -(km1 - eyhx1) * v1, (km3 + eyhx1) * v1);

        // Every A-edge cross-term = cross(V, d) = 2*hx*hy.
        acc = fmaf(dts, 2.0f * hx * hy, acc);
    }

    const float inter_vol = 0.5f * fabsf(acc) * zo;
    const float iou = __fdividef(inter_vol, s - inter_vol);

    float lnum = (m != 0) ? fabsf(ip - (2.0f * iou - 1.0f)) : 0.0f;
    int lcnt = __popc(__ballot_sync(0xffffffffu, m != 0));

    // ---- block reduction ----
#pragma unroll
    for (int off = 16; off > 0; off >>= 1)
        lnum += __shfl_down_sync(0xffffffffu, lnum, off);
    if (lane == 0) { s_red[w] = lnum; s_cnt[w] = lcnt; }
    __syncthreads();
    if (w == 0) {
        lnum = (lane < NW) ? s_red[lane] : 0.0f;
        lcnt = (lane < NW) ? s_cnt[lane] : 0;
#pragma unroll
        for (int off = NW / 2; off > 0; off >>= 1) {
            lnum += __shfl_down_sync(0xffffffffu, lnum, off);
            lcnt += __shfl_down_sync(0xffffffffu, lcnt, off);
        }
        // ---- last-block finalize (threadfence reduction pattern) ----
        if (lane == 0) {
            atomicAdd(&g_num, lnum);
            atomicAdd(&g_cnt, lcnt);
            __threadfence();
            unsigned int old = atomicAdd(&g_done, 1u);
            if (old == NBLK - 1) {
                __threadfence();
                float num = *((volatile float*)&g_num);
                int cnt = *((volatile int*)&g_cnt);
                out[0] = num / ((float)cnt + 1e-4f);
                g_num = 0.0f;       // reset for next graph replay
                g_cnt = 0;
                g_done = 0u;
            }
        }
    }
}

extern "C" void kernel_launch(void* const* d_in, const int* in_sizes, int n_in,
                              void* d_out, int out_size) {
    const float* iou_pred = (const float*)d_in[0];
    const int* mask = (const int*)d_in[1];
    // d_in[2] = ind (unused)
    const float* box_pred = (const float*)d_in[3];
    const float* box_gt = (const float*)d_in[4];
    float* out = (float*)d_out;

    iou_k<<<NBLK, TPB>>>(iou_pred, mask, box_pred, box_gt, out);
}

// round 11
// speedup vs baseline: 1.8634x; 1.0190x over previous
#include <cuda_runtime.h>
#include <math.h>

#define HH 496
#define WW 496
#define HW (HH * WW)
#define BDIM 4
#define NTOT (BDIM * HW)
#define TPB 256
#define BLK_PER_B (HW / TPB)         // 246016/256 = 961 exactly
#define NBLK (BDIM * BLK_PER_B)      // 3844
#define NW (TPB / 32)

__device__ float g_num = 0.0f;
__device__ int g_cnt = 0;
__device__ unsigned int g_done = 0;

__global__ void __launch_bounds__(TPB, 7) iou_k(const float* __restrict__ iou_pred,
                                                const int* __restrict__ mask,
                                                const float* __restrict__ box_pred,
                                                const float* __restrict__ box_gt,
                                                float* __restrict__ out) {
    __shared__ float s_red[NW];
    __shared__ int s_cnt[NW];

    const int tid = threadIdx.x;
    const int lane = tid & 31;
    const int w = tid >> 5;
    const int b = blockIdx.x / BLK_PER_B;
    const int n = blockIdx.x * TPB + tid;
    const int hw = n - b * HW;

    // ---- issue all loads up front: no barriers, maximal MLP ----
    const int m = __ldg(mask + n);
    const float ip = __ldg(iou_pred + n);

    const float* bp = box_pred + (size_t)b * 7 * HW + hw;   // [B,7,H,W] (coalesced)
    const float pa0 = __ldg(bp);
    const float pa1 = __ldg(bp + HW);
    const float pa2 = __ldg(bp + 2 * HW);
    const float pa3 = __ldg(bp + 3 * HW);
    const float pa4 = __ldg(bp + 4 * HW);
    const float pa5 = __ldg(bp + 5 * HW);
    const float pa6 = __ldg(bp + 6 * HW);

    const float* bg = box_gt + (size_t)n * 7;               // [B,H,W,7]
    const float pb0 = __ldg(bg);
    const float pb1 = __ldg(bg + 1);
    const float pb2 = __ldg(bg + 2);
    const float pb3 = __ldg(bg + 3);
    const float pb4 = __ldg(bg + 4);
    const float pb5 = __ldg(bg + 5);
    const float pb6 = __ldg(bg + 6);

    // Predicate now; 'm' dies immediately.
    const unsigned int ball = __ballot_sync(0xffffffffu, m != 0);
    const bool act = (ball >> lane) & 1u;

    // Fold z/volume terms immediately; keep only two live scalars (s, zo).
    const float s = fmaf(pa3 * pa4, pa5, fmaf(pb3 * pb4, pb5, 1e-7f)); // vol_a+vol_b+eps
    const float zo = fmaxf(fminf(pa2 + 0.5f * pa5, pb2 + 0.5f * pb5) -
                           fmaxf(pa2 - 0.5f * pa5, pb2 - 0.5f * pb5), 0.0f);

    // MUFU chains early.
    float sa, ca, sr, cr;
    __sincosf(pa6, &sa, &ca);
    __sincosf(pb6 - pa6, &sr, &cr);

    // Box A's frame: rotate world by -heading_a, center at A. A is the AABB
    // [-hx,hx] x [-hy,hy]; B is a rotated rect centered (rx,ry).
    const float tx = pb0 - pa0, ty = pb1 - pa1;
    const float rx = fmaf(ca, tx, sa * ty);
    const float ry = fmaf(ca, ty, -sa * tx);

    const float hx = 0.5f * pa3, hy = 0.5f * pa4;
    const float lx = 0.5f * pb3, ly = 0.5f * pb4;

    // B corners CCW (c2 = 2T - c0, c3 = 2T - c1; c2/c3 not materialized).
    const float crlx = cr * lx, srlx = sr * lx;
    const float crly = cr * ly, srly = sr * ly;
    const float c0x = rx + crlx - srly, c0y = ry + srlx + crly;
    const float c1x = rx - crlx - srly, c1y = ry - srlx + crly;

    // Edge vectors: e0 = c1-c0, e1 = c2-c1; e2 = -e0, e3 = -e1.
    const float ex0 = -2.0f * crlx, ey0 = -2.0f * srlx;
    const float ex1 =  2.0f * srly, ey1 = -2.0f * crly;

    // Per-edge reciprocals (shared by both passes).
    const float rex0 = __fdividef(1.0f, ex0);
    const float rey0 = __fdividef(1.0f, ey0);
    const float rex1 = __fdividef(1.0f, ex1);
    const float rey1 = __fdividef(1.0f, ey1);

    // Shoelace cross per B edge: k_j = ey_j*c_jx - ex_j*c_jy.
    const float k0 = fmaf(ey0, c0x, -ex0 * c0y);
    const float k1 = fmaf(ey1, c1x, -ex1 * c1y);
    const float k2 = k0 - 2.0f * fmaf(ey0, rx, -ex0 * ry);
    const float k3 = k1 - 2.0f * fmaf(ey1, rx, -ex1 * ry);

    float acc = 0.0f;

    // ---- Pass B first (consumes rex/rey heavily, then they relax) ----
    {
        auto slabB = [&](float cx, float cy, float rex, float rey, float k) {
            float tx1 = (-hx - cx) * rex, tx2 = (hx - cx) * rex;
            float ty1 = (-hy - cy) * rey, ty2 = (hy - cy) * rey;
            float t0 = fmaxf(fmaxf(fminf(tx1, tx2), fminf(ty1, ty2)), 0.0f);
            float t1 = fminf(fminf(fmaxf(tx1, tx2), fmaxf(ty1, ty2)), 1.0f);
            acc = fmaf(fmaxf(t1 - t0, 0.0f), k, acc);
        };
        slabB(c0x, c0y,  rex0,  rey0, k0);
        slabB(c1x, c1y,  rex1,  rey1, k1);
        slabB(2.0f * rx - c0x, 2.0f * ry - c0y, -rex0, -rey0, k2);
        slabB(2.0f * rx - c1x, 2.0f * ry - c1y, -rex1, -rey1, k3);
    }

    // ---- Pass A: A edges vs B rect (strip pairs {0,2},{1,3}, branchless) ----
    {
        const float rhx2 = __fdividef(1.0f, hx + hx);
        const float rhy2 = __fdividef(1.0f, hy + hy);
        const float w0 = rhx2 * rey0, w1 = rhx2 * rey1;   // 1/(2 hx ey_j)
        const float v0 = rhy2 * rex0, v1 = rhy2 * rex1;   // 1/(2 hy ex_j)

        // D_j at A corners: D_j(+-hx, +-hy) = k_j + ex_j*(+-hy) - ey_j*(+-hx).
        const float exhy0 = ex0 * hy, eyhx0 = ey0 * hx;
        const float exhy1 = ex1 * hy, eyhx1 = ey1 * hx;
        const float kp0 = k0 + exhy0, km0 = k0 - exhy0;
        const float kp1 = k1 + exhy1, km1 = k1 - exhy1;
        const float kp2 = k2 - exhy0, km2 = k2 + exhy0;   // ex2 = -ex0
        const float kp3 = k3 - exhy1, km3 = k3 + exhy1;

        auto edgeA = [&](float ta0, float tb0, float ta1, float tb1) -> float {
            float t0 = fmaxf(fmaxf(fminf(ta0, tb0), fminf(ta1, tb1)), 0.0f);
            float t1 = fminf(fminf(fmaxf(ta0, tb0), fmaxf(ta1, tb1)), 1.0f);
            return fmaxf(t1 - t0, 0.0f);
        };

        // Top:    V=(+hx,+hy), d=(-2hx,0):  1/s_j = +w_j
        float dts = edgeA(-(kp0 - eyhx0) * w0, (kp2 + eyhx0) * w0,
                          -(kp1 - eyhx1) * w1, (kp3 + eyhx1) * w1);
        // Left:   V=(-hx,+hy), d=(0,-2hy):  1/s_j = -v_j
        dts += edgeA((kp0 + eyhx0) * v0, -(kp2 - eyhx0) * v0,
                     (kp1 + eyhx1) * v1, -(kp3 - eyhx1) * v1);
        // Bottom: V=(-hx,-hy), d=(+2hx,0):  1/s_j = -w_j
        dts += edgeA((km0 + eyhx0) * w0, -(km2 - eyhx0) * w0,
                     (km1 + eyhx1) * w1, -(km3 - eyhx1) * w1);
        // Right:  V=(+hx,-hy), d=(0,+2hy):  1/s_j = +v_j
        dts += edgeA(-(km0 - eyhx0) * v0, (km2 + eyhx0) * v0,
                     -(km1 - eyhx1) * v1, (km3 + eyhx1) * v1);

        // Every A-edge cross-term = cross(V, d) = 2*hx*hy.
        acc = fmaf(dts, 2.0f * hx * hy, acc);
    }

    const float inter_vol = 0.5f * fabsf(acc) * zo;
    const float iou = __fdividef(inter_vol, s - inter_vol);

    float lnum = act ? fabsf(ip - (2.0f * iou - 1.0f)) : 0.0f;
    int lcnt = __popc(ball);

    // ---- block reduction ----
#pragma unroll
    for (int off = 16; off > 0; off >>= 1)
        lnum += __shfl_down_sync(0xffffffffu, lnum, off);
    if (lane == 0) { s_red[w] = lnum; s_cnt[w] = lcnt; }
    __syncthreads();
    if (w == 0) {
        lnum = (lane < NW) ? s_red[lane] : 0.0f;
        lcnt = (lane < NW) ? s_cnt[lane] : 0;
#pragma unroll
        for (int off = NW / 2; off > 0; off >>= 1) {
            lnum += __shfl_down_sync(0xffffffffu, lnum, off);
            lcnt += __shfl_down_sync(0xffffffffu, lcnt, off);
        }
        // ---- last-block finalize (threadfence reduction pattern) ----
        if (lane == 0) {
            atomicAdd(&g_num, lnum);
            atomicAdd(&g_cnt, lcnt);
            __threadfence();
            unsigned int old = atomicAdd(&g_done, 1u);
            if (old == NBLK - 1) {
                __threadfence();
                float num = *((volatile float*)&g_num);
                int cnt = *((volatile int*)&g_cnt);
                out[0] = num / ((float)cnt + 1e-4f);
                g_num = 0.0f;       // reset for next graph replay
                g_cnt = 0;
                g_done = 0u;
            }
        }
    }
}

extern "C" void kernel_launch(void* const* d_in, const int* in_sizes, int n_in,
                              void* d_out, int out_size) {
    const float* iou_pred = (const float*)d_in[0];
    const int* mask = (const int*)d_in[1];
    // d_in[2] = ind (unused)
    const float* box_pred = (const float*)d_in[3];
    const float* box_gt = (const float*)d_in[4];
    float* out = (float*)d_out;

    iou_k<<<NBLK, TPB>>>(iou_pred, mask, box_pred, box_gt, out);
}